// round 4
// baseline (speedup 1.0000x reference)
#include <cuda_runtime.h>
#include <math.h>

#define NQ       12
#define DEPTH    4
#define DIM      4096
#define NTHREADS 512

// Closed-form composed CNOT-ladder gather (validated in R3): s_after[i] = s_before[gperm(i)]
__device__ __forceinline__ int gperm(int j) {
    return j ^ (j >> 1) ^ ((j & 1) ? 0xC00 : 0);
}

// Fused 2x2 complex gate on register-local bit k of the 8-amp register file.
__device__ __forceinline__ void apply_gate(float re[8], float im[8],
                                           const float* __restrict__ g, int k) {
    const float u00r = g[0], u00i = g[1], u01r = g[2], u01i = g[3];
    const float u10r = g[4], u10i = g[5], u11r = g[6], u11i = g[7];
    const int m = 1 << k;
    #pragma unroll
    for (int r0 = 0; r0 < 8; ++r0) {
        if (r0 & m) continue;
        const int r1 = r0 | m;
        const float a0r = re[r0], a0i = im[r0];
        const float a1r = re[r1], a1i = im[r1];
        re[r0] = u00r * a0r - u00i * a0i + u01r * a1r - u01i * a1i;
        im[r0] = u00r * a0i + u00i * a0r + u01r * a1i + u01i * a1r;
        re[r1] = u10r * a0r - u10i * a0i + u11r * a1r - u11i * a1i;
        im[r1] = u10r * a0i + u10i * a0r + u11r * a1i + u11i * a1r;
    }
}

// Same gate, purely real input state (im == 0): half the FMAs.
__device__ __forceinline__ void apply_gate_real(float re[8], float im[8],
                                                const float* __restrict__ g, int k) {
    const float u00r = g[0], u00i = g[1], u01r = g[2], u01i = g[3];
    const float u10r = g[4], u10i = g[5], u11r = g[6], u11i = g[7];
    const int m = 1 << k;
    #pragma unroll
    for (int r0 = 0; r0 < 8; ++r0) {
        if (r0 & m) continue;
        const int r1 = r0 | m;
        const float a0r = re[r0], a1r = re[r1];
        re[r0] = u00r * a0r + u01r * a1r;
        im[r0] = u00i * a0r + u01i * a1r;
        re[r1] = u10r * a0r + u11r * a1r;
        im[r1] = u10i * a0r + u11i * a1r;
    }
}

__global__ void __launch_bounds__(NTHREADS, 2)
qsim_kernel(const float* __restrict__ input,
            const float* __restrict__ ax,
            const float* __restrict__ ay,
            const float* __restrict__ az,
            float* __restrict__ out)
{
    __shared__ float2 sAmp[DIM];              // 32 KB static exchange buffer
    __shared__ float  sGates[DEPTH * NQ * 8]; // 48 fused gates
    __shared__ float  sRed[32];               // 16-warp reduction scratch

    const int t   = threadIdx.x;              // 9 bits
    const int row = blockIdx.x;

    // ---- fused gate matrices U = Rz * Ry * Rx ----
    if (t < DEPTH * NQ) {
        float sx, cx, sy, cy, sz, cz;
        sincosf(0.5f * ax[t], &sx, &cx);
        sincosf(0.5f * ay[t], &sy, &cy);
        sincosf(0.5f * az[t], &sz, &cz);
        const float m00r = cy * cx, m00i =  sy * sx;
        const float m01r = -sy * cx, m01i = -cy * sx;
        const float m10r =  sy * cx, m10i = -cy * sx;
        const float m11r =  cy * cx, m11i = -sy * sx;
        float* g = &sGates[t * 8];
        g[0] = cz * m00r + sz * m00i;  g[1] = cz * m00i - sz * m00r;
        g[2] = cz * m01r + sz * m01i;  g[3] = cz * m01i - sz * m01r;
        g[4] = cz * m10r - sz * m10i;  g[5] = cz * m10i + sz * m10r;
        g[6] = cz * m11r - sz * m11i;  g[7] = cz * m11i + sz * m11r;
    }

    // ---- load input row (8 elements per thread) + amplitude encoding ----
    float mag[8];
    const float4* inrow = reinterpret_cast<const float4*>(input + (size_t)row * DIM);
    float s1 = 0.f, s2 = 0.f;
    #pragma unroll
    for (int k = 0; k < 2; ++k) {
        const float4 v = inrow[t * 2 + k];
        const float a = fabsf(v.x), b = fabsf(v.y), c = fabsf(v.z), d = fabsf(v.w);
        mag[4 * k + 0] = a; mag[4 * k + 1] = b;
        mag[4 * k + 2] = c; mag[4 * k + 3] = d;
        s1 += (a + b) + (c + d);
        s2 += a * a + b * b + c * c + d * d;
    }
    #pragma unroll
    for (int o = 16; o > 0; o >>= 1) {
        s1 += __shfl_xor_sync(0xffffffffu, s1, o);
        s2 += __shfl_xor_sync(0xffffffffu, s2, o);
    }
    if ((t & 31) == 0) { sRed[t >> 5] = s1; sRed[16 + (t >> 5)] = s2; }
    __syncthreads();   // also publishes sGates
    float S1 = 0.f, S2 = 0.f;
    #pragma unroll
    for (int w = 0; w < 16; ++w) { S1 += sRed[w]; S2 += sRed[16 + w]; }

    // state: thread t holds flat indices [t*8, t*8+8) (Layout0)
    float re[8], im[8];
    if (S1 > 1e-8f) {
        const float sc   = rsqrtf(S1);
        const float norm = sqrtf(S2) * sc;
        const float fs   = (norm > 1e-8f) ? (sc / norm) : sc;
        #pragma unroll
        for (int r = 0; r < 8; ++r) { re[r] = mag[r] * fs; im[r] = 0.f; }
    } else {
        #pragma unroll
        for (int r = 0; r < 8; ++r) { re[r] = 0.015625f; im[r] = 0.f; }
    }

    // ---- thread-constant exchange address pieces ----
    const int tx  = t & 15;                                  // E1 write xor
    const int b1  = ((t >> 3) << 6) | (t & 7);               // L1 base
    const int x1  = ((t >> 3) & 1) << 3;                     // E1 read / E2 write xor hi
    const int b2  = ((t >> 6) << 9) | (t & 63);              // L2 base
    const int x2  = (t >> 3) & 7;                            // E2 read / E3 write xor lo
    const int a3r = t ^ ((t >> 3) & 15);                     // E3 read low bits (swizzled t)
    const int cw  = (9 * ((t >> 4) & 1)) ^ (15 * ((t >> 5) & 1)) ^ (13 * ((t >> 6) & 1));
    const int a4w = t ^ cw;                                  // E4 write low bits
    const int p4  = ((t >> 1) ^ (t >> 2)) & 1;
    const int p5  = ((t >> 2) ^ (t >> 3)) & 1;
    const int p6  = ((t >> 3) ^ (t >> 4)) & 1;
    const int cr  = (9 * p4) ^ (15 * p5) ^ (13 * p6);        // E4 read correction

    #pragma unroll 1
    for (int layer = 0; layer < DEPTH; ++layer) {
        const float* gl = &sGates[layer * NQ * 8];

        // ---- Stage A (L0): reg bit k = global bit k -> qubit 11-k ----
        if (layer == 0) {
            apply_gate_real(re, im, gl + 11 * 8, 0);
            apply_gate(re, im, gl + 10 * 8, 1);
            apply_gate(re, im, gl +  9 * 8, 2);
        } else {
            #pragma unroll
            for (int k = 0; k < 3; ++k) apply_gate(re, im, gl + (11 - k) * 8, k);
        }

        // ---- E1: L0 -> L1, loc(e) = e ^ ((e>>3)&15) ----
        __syncthreads();
        #pragma unroll
        for (int r = 0; r < 8; ++r)
            sAmp[((t << 3) | r) ^ tx] = make_float2(re[r], im[r]);
        __syncthreads();
        #pragma unroll
        for (int r = 0; r < 8; ++r) {
            const float2 v = sAmp[(b1 | (r << 3)) ^ (x1 | r)];
            re[r] = v.x; im[r] = v.y;
        }

        // ---- Stage B (L1): reg bit k = global bit 3+k -> qubit 8-k ----
        #pragma unroll
        for (int k = 0; k < 3; ++k) apply_gate(re, im, gl + (8 - k) * 8, k);

        // ---- E2: L1 -> L2 ----
        __syncthreads();
        #pragma unroll
        for (int r = 0; r < 8; ++r)
            sAmp[(b1 | (r << 3)) ^ (x1 | r)] = make_float2(re[r], im[r]);
        __syncthreads();
        #pragma unroll
        for (int r = 0; r < 8; ++r) {
            const float2 v = sAmp[(b2 | (r << 6)) ^ (((r & 1) << 3) | x2)];
            re[r] = v.x; im[r] = v.y;
        }

        // ---- Stage C (L2): reg bit k = global bit 6+k -> qubit 5-k ----
        #pragma unroll
        for (int k = 0; k < 3; ++k) apply_gate(re, im, gl + (5 - k) * 8, k);

        // ---- E3: L2 -> L3 ----
        __syncthreads();
        #pragma unroll
        for (int r = 0; r < 8; ++r)
            sAmp[(b2 | (r << 6)) ^ (((r & 1) << 3) | x2)] = make_float2(re[r], im[r]);
        __syncthreads();
        #pragma unroll
        for (int r = 0; r < 8; ++r) {
            const float2 v = sAmp[(r << 9) | a3r];
            re[r] = v.x; im[r] = v.y;
        }

        // ---- Stage D (L3): reg bit k = global bit 9+k -> qubit 2-k ----
        #pragma unroll
        for (int k = 0; k < 3; ++k) apply_gate(re, im, gl + (2 - k) * 8, k);

        // ---- E4: L3 -> L0 with CNOT ladder folded in; custom loc4 ----
        __syncthreads();
        #pragma unroll
        for (int r = 0; r < 8; ++r)
            sAmp[(r << 9) | a4w] = make_float2(re[r], im[r]);
        __syncthreads();
        #pragma unroll
        for (int r = 0; r < 8; ++r) {
            const int j = (t << 3) | r;
            const int p = j ^ (j >> 1) ^ ((r & 1) ? 0xC00 : 0);
            const float2 v = sAmp[p ^ cr];
            re[r] = v.x; im[r] = v.y;
        }
    }

    // ---- measurement: |amplitude| ----
    float4* orow = reinterpret_cast<float4*>(out + (size_t)row * DIM);
    #pragma unroll
    for (int k = 0; k < 2; ++k) {
        float4 v;
        v.x = sqrtf(re[4 * k + 0] * re[4 * k + 0] + im[4 * k + 0] * im[4 * k + 0]);
        v.y = sqrtf(re[4 * k + 1] * re[4 * k + 1] + im[4 * k + 1] * im[4 * k + 1]);
        v.z = sqrtf(re[4 * k + 2] * re[4 * k + 2] + im[4 * k + 2] * im[4 * k + 2]);
        v.w = sqrtf(re[4 * k + 3] * re[4 * k + 3] + im[4 * k + 3] * im[4 * k + 3]);
        orow[t * 2 + k] = v;
    }
}

extern "C" void kernel_launch(void* const* d_in, const int* in_sizes, int n_in,
                              void* d_out, int out_size) {
    const float* input = (const float*)d_in[0];
    const float* ax    = (const float*)d_in[1];
    const float* ay    = (const float*)d_in[2];
    const float* az    = (const float*)d_in[3];
    float* out = (float*)d_out;
    const int rows = in_sizes[0] / DIM;
    qsim_kernel<<<rows, NTHREADS>>>(input, ax, ay, az, out);
}